// round 5
// baseline (speedup 1.0000x reference)
#include <cuda_runtime.h>
#include <cuda_bf16.h>
#include <math.h>
#include <stdint.h>

#define N_TOK 4096
#define DIM   128
#define NH    8
#define HD    (NH*DIM)   // 1024

// ---------------------------------------------------------------------------
// Global scratch: q,k,v as [h][n][d] bf16 hi/lo splits; attn output fp32.
// ---------------------------------------------------------------------------
__device__ __align__(128) __nv_bfloat16 g_qhi[(size_t)NH * N_TOK * DIM];
__device__ __align__(128) __nv_bfloat16 g_qlo[(size_t)NH * N_TOK * DIM];
__device__ __align__(128) __nv_bfloat16 g_khi[(size_t)NH * N_TOK * DIM];
__device__ __align__(128) __nv_bfloat16 g_klo[(size_t)NH * N_TOK * DIM];
__device__ __align__(128) __nv_bfloat16 g_vhi[(size_t)NH * N_TOK * DIM];
__device__ __align__(128) __nv_bfloat16 g_vlo[(size_t)NH * N_TOK * DIM];
__device__ __align__(128) float g_attn[(size_t)N_TOK * HD];   // [n][h*128+d]

// ---------------------------------------------------------------------------
// mma.sync / ldmatrix helpers (base-target instructions, sm_80+)
// ---------------------------------------------------------------------------
__device__ __forceinline__ uint32_t smem_u32(const void* p) {
    uint32_t a;
    asm("{ .reg .u64 t; cvta.to.shared.u64 t, %1; cvt.u32.u64 %0, t; }"
        : "=r"(a) : "l"(p));
    return a;
}
__device__ __forceinline__ void ldsm_x4(uint32_t* r, uint32_t addr) {
    asm volatile("ldmatrix.sync.aligned.m8n8.x4.shared.b16 {%0,%1,%2,%3}, [%4];"
        : "=r"(r[0]), "=r"(r[1]), "=r"(r[2]), "=r"(r[3]) : "r"(addr));
}
__device__ __forceinline__ void ldsm_x4_t(uint32_t* r, uint32_t addr) {
    asm volatile("ldmatrix.sync.aligned.m8n8.x4.trans.shared.b16 {%0,%1,%2,%3}, [%4];"
        : "=r"(r[0]), "=r"(r[1]), "=r"(r[2]), "=r"(r[3]) : "r"(addr));
}
__device__ __forceinline__ void mma_bf16(float* c, const uint32_t* a,
                                         uint32_t b0, uint32_t b1) {
    asm volatile("mma.sync.aligned.m16n8k16.row.col.f32.bf16.bf16.f32 "
        "{%0,%1,%2,%3}, {%4,%5,%6,%7}, {%8,%9}, {%0,%1,%2,%3};"
        : "+f"(c[0]), "+f"(c[1]), "+f"(c[2]), "+f"(c[3])
        : "r"(a[0]), "r"(a[1]), "r"(a[2]), "r"(a[3]), "r"(b0), "r"(b1));
}
__device__ __forceinline__ uint32_t pack2bf(float a, float b) {
    unsigned short ua = __bfloat16_as_ushort(__float2bfloat16(a));
    unsigned short ub = __bfloat16_as_ushort(__float2bfloat16(b));
    return (uint32_t)ua | ((uint32_t)ub << 16);
}

// ---------------------------------------------------------------------------
// SGEMM + bias for projections / output.
// dstSel: 0 -> q split, 1 -> k split, 2 -> v split, 3 -> fp32 Cext
// ---------------------------------------------------------------------------
__global__ __launch_bounds__(256) void sgemm_bias_kernel(
    const float* __restrict__ Aext, const float* __restrict__ Bmat,
    const float* __restrict__ bias, float* __restrict__ Cext,
    int M, int Nn, int K, long sB, long sBias, int srcSel, int dstSel)
{
    __shared__ float As[16][68];
    __shared__ float Bs[16][68];

    const float* A = (srcSel == 0) ? Aext : g_attn;
    int z = blockIdx.z;
    const float* B  = Bmat + (long)z * sB;
    const float* bb = bias + (long)z * sBias;

    int row0 = blockIdx.y * 64, col0 = blockIdx.x * 64;
    int tid = threadIdx.x, tx = tid & 15, ty = tid >> 4;
    float acc[4][4] = {};
    int ai = tid >> 2, aj = tid & 3;
    int bi = tid >> 4, bj = tid & 15;

    for (int k0 = 0; k0 < K; k0 += 16) {
        float4 av = *(const float4*)&A[(long)(row0 + ai) * K + k0 + aj * 4];
        As[aj*4+0][ai] = av.x; As[aj*4+1][ai] = av.y;
        As[aj*4+2][ai] = av.z; As[aj*4+3][ai] = av.w;
        *(float4*)&Bs[bi][bj*4] = *(const float4*)&B[(long)(k0 + bi) * Nn + col0 + bj*4];
        __syncthreads();
        #pragma unroll
        for (int kk = 0; kk < 16; ++kk) {
            float4 a = *(float4*)&As[kk][ty*4];
            float4 b = *(float4*)&Bs[kk][tx*4];
            float ar[4] = {a.x,a.y,a.z,a.w}, br[4] = {b.x,b.y,b.z,b.w};
            #pragma unroll
            for (int i = 0; i < 4; ++i)
                #pragma unroll
                for (int j = 0; j < 4; ++j)
                    acc[i][j] = fmaf(ar[i], br[j], acc[i][j]);
        }
        __syncthreads();
    }

    __nv_bfloat16 *hiA = nullptr, *loA = nullptr;
    if (dstSel == 0) { hiA = g_qhi; loA = g_qlo; }
    else if (dstSel == 1) { hiA = g_khi; loA = g_klo; }
    else if (dstSel == 2) { hiA = g_vhi; loA = g_vlo; }

    #pragma unroll
    for (int i = 0; i < 4; ++i) {
        int r = row0 + ty*4 + i;
        #pragma unroll
        for (int j = 0; j < 4; ++j) {
            int c = col0 + tx*4 + j;
            float v = acc[i][j] + bb[c];
            if (dstSel == 3) {
                Cext[(long)r * Nn + c] = v;
            } else {
                long idx = (long)r * Nn + c + (long)z * N_TOK * DIM;
                __nv_bfloat16 hv = __float2bfloat16(v);
                hiA[idx] = hv;
                loA[idx] = __float2bfloat16(v - __bfloat162float(hv));
            }
        }
    }
}

// ---------------------------------------------------------------------------
// Flash attention via mma.sync (bf16 hi/lo split, fp32 accumulate).
// One CTA = one head x 64 v-rows; 4 warps x 16-row stripes. 2 CTAs/SM so the
// sibling CTA's MMA stream fills the tensor pipe during softmax phases.
// j-loop over 32-token q/k tiles (double buffered). P stays in registers.
// smem rows padded: 128 bf16 + 8 pad = 272 B/row (conflict-free ldmatrix).
// ---------------------------------------------------------------------------
#define ROWB   272
#define OFF_VH 0                 // 64 rows hi        (17408 B)
#define OFF_VL 17408             // 64 rows lo
#define OFF_Q  34816             // + buf*17408 ; QH at +0, QL at +8704
#define OFF_K  69632             // + buf*17408 ; KH at +0, KL at +8704
#define SMEM_DYN 104448

__global__ __launch_bounds__(128, 2) void attn_mma_kernel()
{
    extern __shared__ __align__(128) char sm[];
    const uint32_t sb = smem_u32(sm);

    const int tid  = threadIdx.x;
    const int warp = tid >> 5;
    const int lane = tid & 31;
    const int gid  = lane >> 2;        // group id (row within 8)
    const int tg   = lane & 3;         // thread in group (col pair)
    const int h    = blockIdx.y;
    const int i0   = blockIdx.x * 64;

    const uint4* qh = (const uint4*)g_qhi;
    const uint4* ql = (const uint4*)g_qlo;
    const uint4* kh = (const uint4*)g_khi;
    const uint4* kl = (const uint4*)g_klo;
    const uint4* vh = (const uint4*)g_vhi;
    const uint4* vl = (const uint4*)g_vlo;

    // ---- V resident tile: 64 rows x 128 bf16, hi + lo ----
    #pragma unroll
    for (int it = 0; it < 8; ++it) {
        int idx = tid + it * 128;            // 0..1023
        int row = idx >> 4, c = idx & 15;
        int so = row * ROWB + c * 16;
        size_t g = ((size_t)h * N_TOK + i0 + row) * 16 + c;
        *(uint4*)(sm + OFF_VH + so) = vh[g];
        *(uint4*)(sm + OFF_VL + so) = vl[g];
    }
    // ---- Q/K tile buffer 0 (32 rows each) ----
    {
        char* qb = sm + OFF_Q;
        char* kb = sm + OFF_K;
        #pragma unroll
        for (int it = 0; it < 4; ++it) {
            int idx = tid + it * 128;        // 0..511
            int row = idx >> 4, c = idx & 15;
            int so = row * ROWB + c * 16;
            size_t g = ((size_t)h * N_TOK + row) * 16 + c;
            *(uint4*)(qb + so)        = qh[g];
            *(uint4*)(qb + 8704 + so) = ql[g];
            *(uint4*)(kb + so)        = kh[g];
            *(uint4*)(kb + 8704 + so) = kl[g];
        }
    }
    __syncthreads();

    // ldmatrix lane-address components
    const int a_row = warp * 16 + (lane & 15);        // V A-frag row
    const int a_ch  = (lane >> 4) * 8;                // V A-frag col half
    const int b_tok = (lane & 7) + ((lane >> 4) & 1) * 8;   // Q B-frag token
    const int b_kh  = ((lane >> 3) & 1) * 8;                // Q B-frag k half
    const int t_kr  = (lane & 7) + ((lane >> 3) & 1) * 8;   // K(trans) k row
    const int t_nc  = ((lane >> 4) & 1) * 8;                // K(trans) n col

    float ot[16][4];
    #pragma unroll
    for (int n = 0; n < 16; ++n)
        #pragma unroll
        for (int u = 0; u < 4; ++u) ot[n][u] = 0.f;
    float m0 = -INFINITY, m1 = -INFINITY, l0 = 0.f, l1 = 0.f;

    #pragma unroll 1
    for (int j = 0; j < 128; ++j) {
        // ---- prefetch next Q/K tiles into other buffer ----
        if (j < 127) {
            int j0n = (j + 1) * 32;
            char* qb = sm + OFF_Q + ((j + 1) & 1) * 17408;
            char* kb = sm + OFF_K + ((j + 1) & 1) * 17408;
            #pragma unroll
            for (int it = 0; it < 4; ++it) {
                int idx = tid + it * 128;
                int row = idx >> 4, c = idx & 15;
                int so = row * ROWB + c * 16;
                size_t g = ((size_t)h * N_TOK + j0n + row) * 16 + c;
                *(uint4*)(qb + so)        = qh[g];
                *(uint4*)(qb + 8704 + so) = ql[g];
                *(uint4*)(kb + so)        = kh[g];
                *(uint4*)(kb + 8704 + so) = kl[g];
            }
        }

        const uint32_t qbh = sb + OFF_Q + (j & 1) * 17408;
        const uint32_t qbl = qbh + 8704;
        const uint32_t kbh = sb + OFF_K + (j & 1) * 17408;
        const uint32_t kbl = kbh + 8704;

        // ---- S = V . Q^T  (16x32 per warp), 3-term bf16 split ----
        float st[4][4];
        #pragma unroll
        for (int n = 0; n < 4; ++n)
            #pragma unroll
            for (int u = 0; u < 4; ++u) st[n][u] = 0.f;

        #pragma unroll
        for (int ks = 0; ks < 8; ++ks) {
            uint32_t avh[4], avl[4];
            uint32_t va = a_row * ROWB + (ks * 16 + a_ch) * 2;
            ldsm_x4(avh, sb + OFF_VH + va);
            ldsm_x4(avl, sb + OFF_VL + va);
            #pragma unroll
            for (int nt2 = 0; nt2 < 2; ++nt2) {
                uint32_t bqh[4], bql[4];
                uint32_t qa = (nt2 * 16 + b_tok) * ROWB + (ks * 16 + b_kh) * 2;
                ldsm_x4(bqh, qbh + qa);
                ldsm_x4(bql, qbl + qa);
                mma_bf16(st[2*nt2],   avh, bqh[0], bqh[1]);
                mma_bf16(st[2*nt2],   avh, bql[0], bql[1]);
                mma_bf16(st[2*nt2],   avl, bqh[0], bqh[1]);
                mma_bf16(st[2*nt2+1], avh, bqh[2], bqh[3]);
                mma_bf16(st[2*nt2+1], avh, bql[2], bql[3]);
                mma_bf16(st[2*nt2+1], avl, bqh[2], bqh[3]);
            }
        }

        // ---- online softmax (rows gid, gid+8 of this warp's stripe) ----
        float mx0 = st[0][0], mx1 = st[0][2];
        #pragma unroll
        for (int n = 0; n < 4; ++n) {
            mx0 = fmaxf(mx0, fmaxf(st[n][0], st[n][1]));
            mx1 = fmaxf(mx1, fmaxf(st[n][2], st[n][3]));
        }
        mx0 = fmaxf(mx0, __shfl_xor_sync(0xffffffffu, mx0, 1));
        mx0 = fmaxf(mx0, __shfl_xor_sync(0xffffffffu, mx0, 2));
        mx1 = fmaxf(mx1, __shfl_xor_sync(0xffffffffu, mx1, 1));
        mx1 = fmaxf(mx1, __shfl_xor_sync(0xffffffffu, mx1, 2));
        float mn0 = fmaxf(m0, mx0), mn1 = fmaxf(m1, mx1);
        float sc0 = __expf(m0 - mn0), sc1 = __expf(m1 - mn1);
        m0 = mn0; m1 = mn1;
        float sum0 = 0.f, sum1 = 0.f;
        #pragma unroll
        for (int n = 0; n < 4; ++n) {
            st[n][0] = __expf(st[n][0] - m0); sum0 += st[n][0];
            st[n][1] = __expf(st[n][1] - m0); sum0 += st[n][1];
            st[n][2] = __expf(st[n][2] - m1); sum1 += st[n][2];
            st[n][3] = __expf(st[n][3] - m1); sum1 += st[n][3];
        }
        sum0 += __shfl_xor_sync(0xffffffffu, sum0, 1);
        sum0 += __shfl_xor_sync(0xffffffffu, sum0, 2);
        sum1 += __shfl_xor_sync(0xffffffffu, sum1, 1);
        sum1 += __shfl_xor_sync(0xffffffffu, sum1, 2);
        l0 = l0 * sc0 + sum0;
        l1 = l1 * sc1 + sum1;

        // rescale O accumulators
        #pragma unroll
        for (int n = 0; n < 16; ++n) {
            ot[n][0] *= sc0; ot[n][1] *= sc0;
            ot[n][2] *= sc1; ot[n][3] *= sc1;
        }

        // ---- P -> bf16 hi/lo A-frags (registers only) ----
        // A-frag order: a0=(row g, k0-7) a1=(row g+8, k0-7)
        //               a2=(row g, k8-15) a3=(row g+8, k8-15)
        uint32_t ph[2][4], pl[2][4];
        #pragma unroll
        for (int ks2 = 0; ks2 < 2; ++ks2) {
            #pragma unroll
            for (int half = 0; half < 2; ++half) {
                int n = 2 * ks2 + half;
                float v0 = st[n][0], v1 = st[n][1], v2 = st[n][2], v3 = st[n][3];
                __nv_bfloat16 h0 = __float2bfloat16(v0);
                __nv_bfloat16 h1 = __float2bfloat16(v1);
                __nv_bfloat16 h2 = __float2bfloat16(v2);
                __nv_bfloat16 h3 = __float2bfloat16(v3);
                ph[ks2][2*half+0] = (uint32_t)__bfloat16_as_ushort(h0)
                                  | ((uint32_t)__bfloat16_as_ushort(h1) << 16);
                ph[ks2][2*half+1] = (uint32_t)__bfloat16_as_ushort(h2)
                                  | ((uint32_t)__bfloat16_as_ushort(h3) << 16);
                pl[ks2][2*half+0] = pack2bf(v0 - __bfloat162float(h0),
                                            v1 - __bfloat162float(h1));
                pl[ks2][2*half+1] = pack2bf(v2 - __bfloat162float(h2),
                                            v3 - __bfloat162float(h3));
            }
        }

        // ---- O += P . K  (16x128 per warp), 3-term split ----
        #pragma unroll
        for (int ks2 = 0; ks2 < 2; ++ks2) {
            #pragma unroll
            for (int ntp = 0; ntp < 8; ++ntp) {
                uint32_t bkh[4], bkl[4];
                uint32_t ka = (ks2 * 16 + t_kr) * ROWB + (ntp * 16 + t_nc) * 2;
                ldsm_x4_t(bkh, kbh + ka);
                ldsm_x4_t(bkl, kbl + ka);
                mma_bf16(ot[2*ntp],   ph[ks2], bkh[0], bkh[1]);
                mma_bf16(ot[2*ntp],   ph[ks2], bkl[0], bkl[1]);
                mma_bf16(ot[2*ntp],   pl[ks2], bkh[0], bkh[1]);
                mma_bf16(ot[2*ntp+1], ph[ks2], bkh[2], bkh[3]);
                mma_bf16(ot[2*ntp+1], ph[ks2], bkl[2], bkl[3]);
                mma_bf16(ot[2*ntp+1], pl[ks2], bkh[2], bkh[3]);
            }
        }
        __syncthreads();
    }

    // ---- epilogue: normalize, write concat layout ----
    float inv0 = 1.f / l0, inv1 = 1.f / l1;
    int r0 = i0 + warp * 16 + gid;
    int r1 = r0 + 8;
    #pragma unroll
    for (int n = 0; n < 16; ++n) {
        int col = h * 128 + n * 8 + tg * 2;
        *(float2*)&g_attn[(size_t)r0 * HD + col] =
            make_float2(ot[n][0] * inv0, ot[n][1] * inv0);
        *(float2*)&g_attn[(size_t)r1 * HD + col] =
            make_float2(ot[n][2] * inv1, ot[n][3] * inv1);
    }
}

// ---------------------------------------------------------------------------
extern "C" void kernel_launch(void* const* d_in, const int* in_sizes, int n_in,
                              void* d_out, int out_size)
{
    const float* x  = (const float*)d_in[0];
    const float* Wq = (const float*)d_in[1];
    const float* bq = (const float*)d_in[2];
    const float* Wk = (const float*)d_in[3];
    const float* bk = (const float*)d_in[4];
    const float* Wv = (const float*)d_in[5];
    const float* bv = (const float*)d_in[6];
    const float* Wo = (const float*)d_in[7];
    const float* bo = (const float*)d_in[8];
    float* out = (float*)d_out;

    cudaFuncSetAttribute(attn_mma_kernel,
                         cudaFuncAttributeMaxDynamicSharedMemorySize, SMEM_DYN);

    dim3 g1(DIM/64, N_TOK/64, NH);
    sgemm_bias_kernel<<<g1, 256>>>(x, Wq, bq, nullptr, N_TOK, DIM, DIM,
                                   (long)DIM*DIM, DIM, 0, 0);
    sgemm_bias_kernel<<<g1, 256>>>(x, Wk, bk, nullptr, N_TOK, DIM, DIM,
                                   (long)DIM*DIM, DIM, 0, 1);
    sgemm_bias_kernel<<<g1, 256>>>(x, Wv, bv, nullptr, N_TOK, DIM, DIM,
                                   (long)DIM*DIM, DIM, 0, 2);

    dim3 g2(N_TOK/64, NH);
    attn_mma_kernel<<<g2, 128, SMEM_DYN>>>();

    dim3 g3(DIM/64, N_TOK/64, 1);
    sgemm_bias_kernel<<<g3, 256>>>(nullptr, Wo, bo, out, N_TOK, DIM, HD,
                                   0, 0, 1, 3);
}

// round 6
// speedup vs baseline: 1.1028x; 1.1028x over previous
#include <cuda_runtime.h>
#include <cuda_bf16.h>
#include <math.h>
#include <stdint.h>

#define N_TOK 4096
#define DIM   128
#define NH    8
#define HD    (NH*DIM)   // 1024

// ---------------------------------------------------------------------------
// Global scratch: q,k,v as [h][n][d] bf16 hi/lo splits; attn output fp32.
// ---------------------------------------------------------------------------
__device__ __align__(128) __nv_bfloat16 g_qhi[(size_t)NH * N_TOK * DIM];
__device__ __align__(128) __nv_bfloat16 g_qlo[(size_t)NH * N_TOK * DIM];
__device__ __align__(128) __nv_bfloat16 g_khi[(size_t)NH * N_TOK * DIM];
__device__ __align__(128) __nv_bfloat16 g_klo[(size_t)NH * N_TOK * DIM];
__device__ __align__(128) __nv_bfloat16 g_vhi[(size_t)NH * N_TOK * DIM];
__device__ __align__(128) __nv_bfloat16 g_vlo[(size_t)NH * N_TOK * DIM];
__device__ __align__(128) float g_attn[(size_t)N_TOK * HD];   // [n][h*128+d]

// ---------------------------------------------------------------------------
// mma.sync / ldmatrix helpers (base-target instructions, sm_80+)
// ---------------------------------------------------------------------------
__device__ __forceinline__ uint32_t smem_u32(const void* p) {
    uint32_t a;
    asm("{ .reg .u64 t; cvta.to.shared.u64 t, %1; cvt.u32.u64 %0, t; }"
        : "=r"(a) : "l"(p));
    return a;
}
__device__ __forceinline__ void ldsm_x4(uint32_t* r, uint32_t addr) {
    asm volatile("ldmatrix.sync.aligned.m8n8.x4.shared.b16 {%0,%1,%2,%3}, [%4];"
        : "=r"(r[0]), "=r"(r[1]), "=r"(r[2]), "=r"(r[3]) : "r"(addr));
}
__device__ __forceinline__ void ldsm_x4_t(uint32_t* r, uint32_t addr) {
    asm volatile("ldmatrix.sync.aligned.m8n8.x4.trans.shared.b16 {%0,%1,%2,%3}, [%4];"
        : "=r"(r[0]), "=r"(r[1]), "=r"(r[2]), "=r"(r[3]) : "r"(addr));
}
__device__ __forceinline__ void mma_bf16(float* c, const uint32_t* a,
                                         uint32_t b0, uint32_t b1) {
    asm volatile("mma.sync.aligned.m16n8k16.row.col.f32.bf16.bf16.f32 "
        "{%0,%1,%2,%3}, {%4,%5,%6,%7}, {%8,%9}, {%0,%1,%2,%3};"
        : "+f"(c[0]), "+f"(c[1]), "+f"(c[2]), "+f"(c[3])
        : "r"(a[0]), "r"(a[1]), "r"(a[2]), "r"(a[3]), "r"(b0), "r"(b1));
}
__device__ __forceinline__ uint32_t pack2bf(float a, float b) {
    unsigned short ua = __bfloat16_as_ushort(__float2bfloat16(a));
    unsigned short ub = __bfloat16_as_ushort(__float2bfloat16(b));
    return (uint32_t)ua | ((uint32_t)ub << 16);
}

// ---------------------------------------------------------------------------
// SGEMM + bias for projections / output.
// dstSel: 0 -> q split, 1 -> k split, 2 -> v split, 3 -> fp32 Cext
// ---------------------------------------------------------------------------
__global__ __launch_bounds__(256) void sgemm_bias_kernel(
    const float* __restrict__ Aext, const float* __restrict__ Bmat,
    const float* __restrict__ bias, float* __restrict__ Cext,
    int M, int Nn, int K, long sB, long sBias, int srcSel, int dstSel)
{
    __shared__ float As[16][68];
    __shared__ float Bs[16][68];

    const float* A = (srcSel == 0) ? Aext : g_attn;
    int z = blockIdx.z;
    const float* B  = Bmat + (long)z * sB;
    const float* bb = bias + (long)z * sBias;

    int row0 = blockIdx.y * 64, col0 = blockIdx.x * 64;
    int tid = threadIdx.x, tx = tid & 15, ty = tid >> 4;
    float acc[4][4] = {};
    int ai = tid >> 2, aj = tid & 3;
    int bi = tid >> 4, bj = tid & 15;

    for (int k0 = 0; k0 < K; k0 += 16) {
        float4 av = *(const float4*)&A[(long)(row0 + ai) * K + k0 + aj * 4];
        As[aj*4+0][ai] = av.x; As[aj*4+1][ai] = av.y;
        As[aj*4+2][ai] = av.z; As[aj*4+3][ai] = av.w;
        *(float4*)&Bs[bi][bj*4] = *(const float4*)&B[(long)(k0 + bi) * Nn + col0 + bj*4];
        __syncthreads();
        #pragma unroll
        for (int kk = 0; kk < 16; ++kk) {
            float4 a = *(float4*)&As[kk][ty*4];
            float4 b = *(float4*)&Bs[kk][tx*4];
            float ar[4] = {a.x,a.y,a.z,a.w}, br[4] = {b.x,b.y,b.z,b.w};
            #pragma unroll
            for (int i = 0; i < 4; ++i)
                #pragma unroll
                for (int j = 0; j < 4; ++j)
                    acc[i][j] = fmaf(ar[i], br[j], acc[i][j]);
        }
        __syncthreads();
    }

    __nv_bfloat16 *hiA = nullptr, *loA = nullptr;
    if (dstSel == 0) { hiA = g_qhi; loA = g_qlo; }
    else if (dstSel == 1) { hiA = g_khi; loA = g_klo; }
    else if (dstSel == 2) { hiA = g_vhi; loA = g_vlo; }

    #pragma unroll
    for (int i = 0; i < 4; ++i) {
        int r = row0 + ty*4 + i;
        #pragma unroll
        for (int j = 0; j < 4; ++j) {
            int c = col0 + tx*4 + j;
            float v = acc[i][j] + bb[c];
            if (dstSel == 3) {
                Cext[(long)r * Nn + c] = v;
            } else {
                long idx = (long)r * Nn + c + (long)z * N_TOK * DIM;
                __nv_bfloat16 hv = __float2bfloat16(v);
                hiA[idx] = hv;
                loA[idx] = __float2bfloat16(v - __bfloat162float(hv));
            }
        }
    }
}

// ---------------------------------------------------------------------------
// Flash attention via mma.sync (bf16 hi/lo split, fp32 accumulate).
// One CTA = one head x 128 v-rows; 8 warps x 16-row stripes.
// j-loop over 64-token q/k tiles (double buffered). P stays in registers.
// MMA issue is TERM-MAJOR so consecutive MMAs hit different accumulators
// (same-accumulator issue distance 8 in S-loop, 4 in O-loop) -- hides HMMA
// latency that bound rounds 4/5 at tensor~48%.
// smem rows padded: 128 bf16 + 8 pad = 272 B/row (conflict-free ldmatrix).
// ---------------------------------------------------------------------------
#define ROWB   272
#define OFF_VH 0
#define OFF_VL 34816
#define OFF_Q  69632             // + buf*34816 ; QH at +0, QL at +17408
#define OFF_K  139264            // + buf*34816 ; KH at +0, KL at +17408
#define SMEM_DYN 208896

__global__ __launch_bounds__(256, 1) void attn_mma_kernel()
{
    extern __shared__ __align__(128) char sm[];
    const uint32_t sb = smem_u32(sm);

    const int tid  = threadIdx.x;
    const int warp = tid >> 5;
    const int lane = tid & 31;
    const int gid  = lane >> 2;        // group id (row within 8)
    const int tg   = lane & 3;         // thread in group (col pair)
    const int h    = blockIdx.y;
    const int i0   = blockIdx.x * 128;

    const uint4* qh = (const uint4*)g_qhi;
    const uint4* ql = (const uint4*)g_qlo;
    const uint4* kh = (const uint4*)g_khi;
    const uint4* kl = (const uint4*)g_klo;
    const uint4* vh = (const uint4*)g_vhi;
    const uint4* vl = (const uint4*)g_vlo;

    // ---- V resident tile: 128 rows x 128 bf16, hi + lo ----
    #pragma unroll
    for (int it = 0; it < 8; ++it) {
        int idx = tid + it * 256;            // 0..2047
        int row = idx >> 4, c = idx & 15;
        int so = row * ROWB + c * 16;
        size_t g = ((size_t)h * N_TOK + i0 + row) * 16 + c;
        *(uint4*)(sm + OFF_VH + so) = vh[g];
        *(uint4*)(sm + OFF_VL + so) = vl[g];
    }
    // ---- Q/K tile buffer 0 ----
    {
        char* qb = sm + OFF_Q;
        char* kb = sm + OFF_K;
        #pragma unroll
        for (int it = 0; it < 4; ++it) {
            int idx = tid + it * 256;        // 0..1023
            int row = idx >> 4, c = idx & 15;
            int so = row * ROWB + c * 16;
            size_t g = ((size_t)h * N_TOK + row) * 16 + c;
            *(uint4*)(qb + so)         = qh[g];
            *(uint4*)(qb + 17408 + so) = ql[g];
            *(uint4*)(kb + so)         = kh[g];
            *(uint4*)(kb + 17408 + so) = kl[g];
        }
    }
    __syncthreads();

    // ldmatrix lane-address components
    const int a_row = warp * 16 + (lane & 15);        // V A-frag row
    const int a_ch  = (lane >> 4) * 8;                // V A-frag col half
    const int b_tok = (lane & 7) + ((lane >> 4) & 1) * 8;   // Q B-frag token
    const int b_kh  = ((lane >> 3) & 1) * 8;                // Q B-frag k half
    const int t_kr  = (lane & 7) + ((lane >> 3) & 1) * 8;   // K(trans) k row
    const int t_nc  = ((lane >> 4) & 1) * 8;                // K(trans) n col

    float ot[16][4];
    #pragma unroll
    for (int n = 0; n < 16; ++n)
        #pragma unroll
        for (int u = 0; u < 4; ++u) ot[n][u] = 0.f;
    float m0 = -INFINITY, m1 = -INFINITY, l0 = 0.f, l1 = 0.f;

    #pragma unroll 1
    for (int j = 0; j < 64; ++j) {
        // ---- prefetch next Q/K tiles into other buffer ----
        if (j < 63) {
            int j0n = (j + 1) * 64;
            char* qb = sm + OFF_Q + ((j + 1) & 1) * 34816;
            char* kb = sm + OFF_K + ((j + 1) & 1) * 34816;
            #pragma unroll
            for (int it = 0; it < 4; ++it) {
                int idx = tid + it * 256;
                int row = idx >> 4, c = idx & 15;
                int so = row * ROWB + c * 16;
                size_t g = ((size_t)h * N_TOK + j0n + row) * 16 + c;
                *(uint4*)(qb + so)         = qh[g];
                *(uint4*)(qb + 17408 + so) = ql[g];
                *(uint4*)(kb + so)         = kh[g];
                *(uint4*)(kb + 17408 + so) = kl[g];
            }
        }

        const uint32_t qbh = sb + OFF_Q + (j & 1) * 34816;
        const uint32_t qbl = qbh + 17408;
        const uint32_t kbh = sb + OFF_K + (j & 1) * 34816;
        const uint32_t kbl = kbh + 17408;

        // ---- S = V . Q^T  (16x64 per warp), 3-term bf16 split ----
        // Term-major issue: same-accumulator distance = 8 MMAs.
        float st[8][4];
        #pragma unroll
        for (int n = 0; n < 8; ++n)
            #pragma unroll
            for (int u = 0; u < 4; ++u) st[n][u] = 0.f;

        #pragma unroll
        for (int ks = 0; ks < 8; ++ks) {
            uint32_t avh[4], avl[4];
            uint32_t va = a_row * ROWB + (ks * 16 + a_ch) * 2;
            ldsm_x4(avh, sb + OFF_VH + va);
            ldsm_x4(avl, sb + OFF_VL + va);
            uint32_t bqh[4][4], bql[4][4];
            #pragma unroll
            for (int nt2 = 0; nt2 < 4; ++nt2) {
                uint32_t qa = (nt2 * 16 + b_tok) * ROWB + (ks * 16 + b_kh) * 2;
                ldsm_x4(bqh[nt2], qbh + qa);
                ldsm_x4(bql[nt2], qbl + qa);
            }
            // term hi*hi
            #pragma unroll
            for (int nt2 = 0; nt2 < 4; ++nt2) {
                mma_bf16(st[2*nt2],   avh, bqh[nt2][0], bqh[nt2][1]);
                mma_bf16(st[2*nt2+1], avh, bqh[nt2][2], bqh[nt2][3]);
            }
            // term hi*lo
            #pragma unroll
            for (int nt2 = 0; nt2 < 4; ++nt2) {
                mma_bf16(st[2*nt2],   avh, bql[nt2][0], bql[nt2][1]);
                mma_bf16(st[2*nt2+1], avh, bql[nt2][2], bql[nt2][3]);
            }
            // term lo*hi
            #pragma unroll
            for (int nt2 = 0; nt2 < 4; ++nt2) {
                mma_bf16(st[2*nt2],   avl, bqh[nt2][0], bqh[nt2][1]);
                mma_bf16(st[2*nt2+1], avl, bqh[nt2][2], bqh[nt2][3]);
            }
        }

        // ---- online softmax (rows gid, gid+8 of this warp's stripe) ----
        float mx0 = st[0][0], mx1 = st[0][2];
        #pragma unroll
        for (int n = 0; n < 8; ++n) {
            mx0 = fmaxf(mx0, fmaxf(st[n][0], st[n][1]));
            mx1 = fmaxf(mx1, fmaxf(st[n][2], st[n][3]));
        }
        mx0 = fmaxf(mx0, __shfl_xor_sync(0xffffffffu, mx0, 1));
        mx0 = fmaxf(mx0, __shfl_xor_sync(0xffffffffu, mx0, 2));
        mx1 = fmaxf(mx1, __shfl_xor_sync(0xffffffffu, mx1, 1));
        mx1 = fmaxf(mx1, __shfl_xor_sync(0xffffffffu, mx1, 2));
        float mn0 = fmaxf(m0, mx0), mn1 = fmaxf(m1, mx1);
        float sc0 = __expf(m0 - mn0), sc1 = __expf(m1 - mn1);
        m0 = mn0; m1 = mn1;
        float sum0 = 0.f, sum1 = 0.f;
        #pragma unroll
        for (int n = 0; n < 8; ++n) {
            st[n][0] = __expf(st[n][0] - m0); sum0 += st[n][0];
            st[n][1] = __expf(st[n][1] - m0); sum0 += st[n][1];
            st[n][2] = __expf(st[n][2] - m1); sum1 += st[n][2];
            st[n][3] = __expf(st[n][3] - m1); sum1 += st[n][3];
        }
        sum0 += __shfl_xor_sync(0xffffffffu, sum0, 1);
        sum0 += __shfl_xor_sync(0xffffffffu, sum0, 2);
        sum1 += __shfl_xor_sync(0xffffffffu, sum1, 1);
        sum1 += __shfl_xor_sync(0xffffffffu, sum1, 2);
        l0 = l0 * sc0 + sum0;
        l1 = l1 * sc1 + sum1;

        // rescale O accumulators
        #pragma unroll
        for (int n = 0; n < 16; ++n) {
            ot[n][0] *= sc0; ot[n][1] *= sc0;
            ot[n][2] *= sc1; ot[n][3] *= sc1;
        }

        // ---- P -> bf16 hi/lo A-frags (registers only) ----
        // A-frag order: a0=(row g, k0-7) a1=(row g+8, k0-7)
        //               a2=(row g, k8-15) a3=(row g+8, k8-15)
        uint32_t ph[4][4], pl[4][4];
        #pragma unroll
        for (int ks2 = 0; ks2 < 4; ++ks2) {
            #pragma unroll
            for (int half = 0; half < 2; ++half) {
                int n = 2 * ks2 + half;
                float v0 = st[n][0], v1 = st[n][1], v2 = st[n][2], v3 = st[n][3];
                __nv_bfloat16 h0 = __float2bfloat16(v0);
                __nv_bfloat16 h1 = __float2bfloat16(v1);
                __nv_bfloat16 h2 = __float2bfloat16(v2);
                __nv_bfloat16 h3 = __float2bfloat16(v3);
                ph[ks2][2*half+0] = (uint32_t)__bfloat16_as_ushort(h0)
                                  | ((uint32_t)__bfloat16_as_ushort(h1) << 16);
                ph[ks2][2*half+1] = (uint32_t)__bfloat16_as_ushort(h2)
                                  | ((uint32_t)__bfloat16_as_ushort(h3) << 16);
                pl[ks2][2*half+0] = pack2bf(v0 - __bfloat162float(h0),
                                            v1 - __bfloat162float(h1));
                pl[ks2][2*half+1] = pack2bf(v2 - __bfloat162float(h2),
                                            v3 - __bfloat162float(h3));
            }
        }

        // ---- O += P . K  (16x128 per warp), 3-term split ----
        // Process ntp pairs; term-major issue over 4 accumulators.
        #pragma unroll
        for (int ks2 = 0; ks2 < 4; ++ks2) {
            #pragma unroll
            for (int pp = 0; pp < 4; ++pp) {
                uint32_t bh0[4], bl0[4], bh1[4], bl1[4];
                uint32_t ka0 = (ks2 * 16 + t_kr) * ROWB + ((2*pp) * 16 + t_nc) * 2;
                uint32_t ka1 = ka0 + 32;     // ntp+1 -> +16 cols = +32 bytes
                ldsm_x4_t(bh0, kbh + ka0);
                ldsm_x4_t(bl0, kbl + ka0);
                ldsm_x4_t(bh1, kbh + ka1);
                ldsm_x4_t(bl1, kbl + ka1);
                // term ph*kh
                mma_bf16(ot[4*pp+0], ph[ks2], bh0[0], bh0[1]);
                mma_bf16(ot[4*pp+1], ph[ks2], bh0[2], bh0[3]);
                mma_bf16(ot[4*pp+2], ph[ks2], bh1[0], bh1[1]);
                mma_bf16(ot[4*pp+3], ph[ks2], bh1[2], bh1[3]);
                // term ph*kl
                mma_bf16(ot[4*pp+0], ph[ks2], bl0[0], bl0[1]);
                mma_bf16(ot[4*pp+1], ph[ks2], bl0[2], bl0[3]);
                mma_bf16(ot[4*pp+2], ph[ks2], bl1[0], bl1[1]);
                mma_bf16(ot[4*pp+3], ph[ks2], bl1[2], bl1[3]);
                // term pl*kh
                mma_bf16(ot[4*pp+0], pl[ks2], bh0[0], bh0[1]);
                mma_bf16(ot[4*pp+1], pl[ks2], bh0[2], bh0[3]);
                mma_bf16(ot[4*pp+2], pl[ks2], bh1[0], bh1[1]);
                mma_bf16(ot[4*pp+3], pl[ks2], bh1[2], bh1[3]);
            }
        }
        __syncthreads();
    }

    // ---- epilogue: normalize, write concat layout ----
    float inv0 = 1.f / l0, inv1 = 1.f / l1;
    int r0 = i0 + warp * 16 + gid;
    int r1 = r0 + 8;
    #pragma unroll
    for (int n = 0; n < 16; ++n) {
        int col = h * 128 + n * 8 + tg * 2;
        *(float2*)&g_attn[(size_t)r0 * HD + col] =
            make_float2(ot[n][0] * inv0, ot[n][1] * inv0);
        *(float2*)&g_attn[(size_t)r1 * HD + col] =
            make_float2(ot[n][2] * inv1, ot[n][3] * inv1);
    }
}

// ---------------------------------------------------------------------------
extern "C" void kernel_launch(void* const* d_in, const int* in_sizes, int n_in,
                              void* d_out, int out_size)
{
    const float* x  = (const float*)d_in[0];
    const float* Wq = (const float*)d_in[1];
    const float* bq = (const float*)d_in[2];
    const float* Wk = (const float*)d_in[3];
    const float* bk = (const float*)d_in[4];
    const float* Wv = (const float*)d_in[5];
    const float* bv = (const float*)d_in[6];
    const float* Wo = (const float*)d_in[7];
    const float* bo = (const float*)d_in[8];
    float* out = (float*)d_out;

    cudaFuncSetAttribute(attn_mma_kernel,
                         cudaFuncAttributeMaxDynamicSharedMemorySize, SMEM_DYN);

    dim3 g1(DIM/64, N_TOK/64, NH);
    sgemm_bias_kernel<<<g1, 256>>>(x, Wq, bq, nullptr, N_TOK, DIM, DIM,
                                   (long)DIM*DIM, DIM, 0, 0);
    sgemm_bias_kernel<<<g1, 256>>>(x, Wk, bk, nullptr, N_TOK, DIM, DIM,
                                   (long)DIM*DIM, DIM, 0, 1);
    sgemm_bias_kernel<<<g1, 256>>>(x, Wv, bv, nullptr, N_TOK, DIM, DIM,
                                   (long)DIM*DIM, DIM, 0, 2);

    dim3 g2(N_TOK/128, NH);
    attn_mma_kernel<<<g2, 256, SMEM_DYN>>>();

    dim3 g3(DIM/64, N_TOK/64, 1);
    sgemm_bias_kernel<<<g3, 256>>>(nullptr, Wo, bo, out, N_TOK, DIM, HD,
                                   0, 0, 1, 3);
}